// round 8
// baseline (speedup 1.0000x reference)
#include <cuda_runtime.h>
#include <cstdint>

// LGA: out[n,c,h,w] = sum_{i,j in 5x5} in1[n,c,h+i-2,w+j-2] * in2[n,i*5+j,h,w]
// Shapes fixed: in1 [4,32,384,768] f32, in2 [4,25,384,768] f32.
//
// Round-8: warp-private pipelines -> ZERO block barriers.
//  - Each warp owns a 32x4-px tile (8 lanes x 4 px wide, 4 rows tall) and its
//    own cp.async smem ring (4 stages x channel pairs). Producer == consumer
//    warp, so sync is cp.async.wait_group + __syncwarp only.
//  - Per channel a warp stages an 8-row x 40-float halo (16B-aligned chunks,
//    zero-fill at edges). 100 per-pixel taps stay in registers across all 32
//    channels; compute is packed fma.rn.f32x2 (exact f32 semantics).

#define NDIM 4
#define CDIM 32
#define HDIM 384
#define WDIM 768
#define KTAPS 25
#define PLANE (HDIM * WDIM)

#define NTHR 128
#define NWARP 4
#define WARP_W 32                      // px per warp tile (8 lanes * 4 px)
#define WARP_H 4                       // rows per warp tile
#define TILE_W WARP_W                  // block = 4 warps stacked vertically
#define TILE_H (WARP_H * NWARP)        // 16
#define SROWS 8                        // WARP_H + 4 halo rows
#define SPITCH 40                      // floats per staged row (160 B, 16B-mult)
#define CH_ELEMS (SROWS * SPITCH)      // 320 floats per channel
#define STAGES 4                       // ring of channel PAIRS
#define NPAIR (CDIM / 2)               // 16
#define CHUNKS_PER_ROW 10              // 10 x 16B = 40 floats
#define NCHUNK (SROWS * CHUNKS_PER_ROW)  // 80 chunks per channel

typedef unsigned long long u64;

__device__ __forceinline__ uint32_t smem_u32(const void* p) {
    return (uint32_t)__cvta_generic_to_shared(p);
}
__device__ __forceinline__ void cp_async16(uint32_t dst, const float* src, int sz) {
    asm volatile("cp.async.cg.shared.global [%0], [%1], 16, %2;\n"
                 :: "r"(dst), "l"(src), "r"(sz));
}
__device__ __forceinline__ void cp_commit() {
    asm volatile("cp.async.commit_group;\n" ::: "memory");
}
__device__ __forceinline__ void cp_wait2() {
    asm volatile("cp.async.wait_group 2;\n" ::: "memory");
}
__device__ __forceinline__ u64 pack2(float lo, float hi) {
    u64 r;
    asm("mov.b64 %0, {%1, %2};" : "=l"(r) : "f"(lo), "f"(hi));
    return r;
}
__device__ __forceinline__ void unpack2(u64 v, float& lo, float& hi) {
    asm("mov.b64 {%0, %1}, %2;" : "=f"(lo), "=f"(hi) : "l"(v));
}
__device__ __forceinline__ void fma2(u64& acc, u64 a, u64 b) {
    asm("fma.rn.f32x2 %0, %1, %2, %0;" : "+l"(acc) : "l"(a), "l"(b));
}

__global__ __launch_bounds__(NTHR, 3)
void lga_kernel(const float* __restrict__ in1,
                const float* __restrict__ in2,
                float* __restrict__ out) {
    // per-warp ring: [warp][stage][channel-in-pair][320 floats]
    __shared__ __align__(16) float ring[NWARP][STAGES][2][CH_ELEMS];

    const int tid  = threadIdx.x;
    const int wrp  = tid >> 5;             // 0..3
    const int lane = tid & 31;
    const int lx   = lane & 7;             // 0..7  (column group)
    const int ly   = lane >> 3;            // 0..3  (row within warp tile)

    const int wbase = blockIdx.x * TILE_W;                 // tile cols (32)
    const int hwarp = blockIdx.y * TILE_H + wrp * WARP_H;  // warp's first row
    const int n = blockIdx.z;

    const int h  = hwarp + ly;              // output row of this lane
    const int w0 = wbase + 4 * lx;          // first of 4 output cols

    // ---- 25 per-pixel weight quads -> 50 packed f32x2 registers ----
    u64 w01[KTAPS], w23[KTAPS];
    {
        const float* wp = in2 + ((size_t)n * KTAPS * HDIM + h) * WDIM + w0;
#pragma unroll
        for (int t = 0; t < KTAPS; t++) {
            float4 v = __ldcs((const float4*)(wp + (size_t)t * PLANE));
            w01[t] = pack2(v.x, v.y);
            w23[t] = pack2(v.z, v.w);
        }
    }

    // ---- copy roles: up to 3 16B chunks per lane per channel (80 total) ----
    const float* in1n = in1 + (size_t)n * CDIM * PLANE;
    int  goff[3], cpsz[3], soff[3];
    bool act[3];
#pragma unroll
    for (int j = 0; j < 3; j++) {
        int k = lane + 32 * j;
        act[j] = (k < NCHUNK);
        int r  = k / CHUNKS_PER_ROW;
        int ch = k - r * CHUNKS_PER_ROW;
        int gy  = hwarp - 2 + r;
        int gx0 = wbase - 4 + 4 * ch;       // 16B-aligned
        bool v = act[j] && (gy >= 0) && (gy < HDIM) &&
                 (gx0 >= 0) && (gx0 + 3 < WDIM);
        goff[j] = v ? (gy * WDIM + gx0) : 0;
        cpsz[j] = v ? 16 : 0;
        soff[j] = r * SPITCH + 4 * ch;
    }

    float* po = out + (size_t)n * CDIM * PLANE + (size_t)h * WDIM + w0;

    // smem byte addresses of each stage/half base
    uint32_t sbase[STAGES][2];
#pragma unroll
    for (int s = 0; s < STAGES; s++) {
        sbase[s][0] = smem_u32(&ring[wrp][s][0][0]);
        sbase[s][1] = smem_u32(&ring[wrp][s][1][0]);
    }

    // issue the copy of channel pair p into stage s (one commit group)
    auto issue = [&](int p, int s) {
#pragma unroll
        for (int half = 0; half < 2; half++) {
            const float* src = in1n + (size_t)(2 * p + half) * PLANE;
            uint32_t d = sbase[s][half];
#pragma unroll
            for (int j = 0; j < 3; j++)
                if (act[j]) cp_async16(d + 4 * soff[j], src + goff[j], cpsz[j]);
        }
        cp_commit();
    };

    // ---- prologue: pairs 0..2 (channels 0..5) in flight ----
    issue(0, 0);
    issue(1, 1);
    issue(2, 2);

#pragma unroll 1
    for (int p = 0; p < NPAIR; p++) {
        const int s = p & (STAGES - 1);

        cp_wait2();          // this lane's copies for pair p have landed
        __syncwarp();        // publish all lanes' copies; fences ring reuse

        if (p + 3 < NPAIR) issue(p + 3, (p + 3) & (STAGES - 1));
        else               cp_commit();   // keep wait-count math fixed

        // ---- compute both channels of the pair (4 px each) ----
#pragma unroll
        for (int half = 0; half < 2; half++) {
            // staged col0 = wbase-4; window starts at w0-2 -> 4*lx+2
            const float* basep = &ring[wrp][s][half][ly * SPITCH + 4 * lx + 2];
            u64 acc01 = 0, acc23 = 0;
#pragma unroll
            for (int i = 0; i < 5; i++) {
                const float* rp = basep + i * SPITCH;
                float2 A  = *(const float2*)(rp);       // d0 d1
                float4 Bq = *(const float4*)(rp + 2);   // d2..d5
                float2 C  = *(const float2*)(rp + 6);   // d6 d7

                u64 p01 = pack2(A.x, A.y);
                u64 p12 = pack2(A.y, Bq.x);
                u64 p23 = pack2(Bq.x, Bq.y);
                u64 p34 = pack2(Bq.y, Bq.z);
                u64 p45 = pack2(Bq.z, Bq.w);
                u64 p56 = pack2(Bq.w, C.x);
                u64 p67 = pack2(C.x, C.y);

                const u64* wr01 = &w01[5 * i];
                const u64* wr23 = &w23[5 * i];
                fma2(acc01, p01, wr01[0]);
                fma2(acc23, p23, wr23[0]);
                fma2(acc01, p12, wr01[1]);
                fma2(acc23, p34, wr23[1]);
                fma2(acc01, p23, wr01[2]);
                fma2(acc23, p45, wr23[2]);
                fma2(acc01, p34, wr01[3]);
                fma2(acc23, p56, wr23[3]);
                fma2(acc01, p45, wr01[4]);
                fma2(acc23, p67, wr23[4]);
            }
            float4 o;
            unpack2(acc01, o.x, o.y);
            unpack2(acc23, o.z, o.w);
            __stcs((float4*)(po + (size_t)(2 * p + half) * PLANE), o);
        }
    }
}

extern "C" void kernel_launch(void* const* d_in, const int* in_sizes, int n_in,
                              void* d_out, int out_size) {
    const float* in1 = (const float*)d_in[0];
    const float* in2 = (const float*)d_in[1];
    float* out = (float*)d_out;

    dim3 block(NTHR);
    dim3 grid(WDIM / TILE_W, HDIM / TILE_H, NDIM);  // 24 x 24 x 4
    lga_kernel<<<grid, block>>>(in1, in2, out);
}

// round 9
// speedup vs baseline: 1.0693x; 1.0693x over previous
#include <cuda_runtime.h>
#include <cstdint>

// LGA: out[n,c,h,w] = sum_{i,j in 5x5} in1[n,c,h+i-2,w+j-2] * in2[n,i*5+j,h,w]
// Shapes fixed: in1 [4,32,384,768] f32, in2 [4,25,384,768] f32.
//
// Round-9 = round-7 pipeline (4-stage cp.async ring of channel pairs, one
// barrier per 2 channels) + restructured compute:
//  - swapped-accumulator trick: acc01=(px0,px1) handles even taps with the
//    naturally aligned pairs (d0,d1)(d2,d3)(d4,d5); acc10=(px1,px0) handles
//    the two middle odd-tap terms with the aligned (d2,d3)/(d4,d5) pairs; the
//    two leftover odd-tap terms go to scalar FFMA side accumulators.
//    -> ZERO per-row register packs (round-7 spent ~30 MOVs/channel on them),
//    and 6 independent FMA chains per channel instead of 2.

#define NDIM 4
#define CDIM 32
#define HDIM 384
#define WDIM 768
#define KTAPS 25
#define PLANE (HDIM * WDIM)

#define BX 16
#define BY 8
#define NTHR (BX * BY)                // 128
#define TILE_W 64                     // 16 threads * 4 px
#define TILE_H 8
#define SROWS (TILE_H + 4)            // 12
#define SPITCH 72                     // floats per smem row (288 B)
#define STAGE_ELEMS (SROWS * SPITCH)  // 864
#define STAGES 4                      // ring of channel PAIRS
#define NPAIR (CDIM / 2)              // 16
#define CHUNKS_PER_ROW 18             // 18 x 16B = 72 floats
#define NCHUNK (SROWS * CHUNKS_PER_ROW)  // 216

typedef unsigned long long u64;

__device__ __forceinline__ uint32_t smem_u32(const void* p) {
    return (uint32_t)__cvta_generic_to_shared(p);
}
__device__ __forceinline__ void cp_async16(uint32_t dst, const float* src, int sz) {
    asm volatile("cp.async.cg.shared.global [%0], [%1], 16, %2;\n"
                 :: "r"(dst), "l"(src), "r"(sz));
}
__device__ __forceinline__ void cp_commit() {
    asm volatile("cp.async.commit_group;\n" ::: "memory");
}
__device__ __forceinline__ void cp_wait2() {
    asm volatile("cp.async.wait_group 2;\n" ::: "memory");
}
__device__ __forceinline__ u64 pack2(float lo, float hi) {
    u64 r;
    asm("mov.b64 %0, {%1, %2};" : "=l"(r) : "f"(lo), "f"(hi));
    return r;
}
__device__ __forceinline__ void unpack2(u64 v, float& lo, float& hi) {
    asm("mov.b64 {%0, %1}, %2;" : "=f"(lo), "=f"(hi) : "l"(v));
}
__device__ __forceinline__ void fma2(u64& acc, u64 a, u64 b) {
    asm("fma.rn.f32x2 %0, %1, %2, %0;" : "+l"(acc) : "l"(a), "l"(b));
}

__global__ __launch_bounds__(NTHR, 3)
void lga_kernel(const float* __restrict__ in1,
                const float* __restrict__ in2,
                float* __restrict__ out) {
    __shared__ __align__(16) float ring[STAGES][2][STAGE_ELEMS];

    const int tx = threadIdx.x;            // 0..15
    const int ty = threadIdx.y;            // 0..7
    const int tid = ty * BX + tx;
    const int wbase = blockIdx.x * TILE_W;
    const int hbase = blockIdx.y * TILE_H;
    const int n = blockIdx.z;

    const int h = hbase + ty;              // output row
    const int w0 = wbase + 4 * tx;         // first of 4 output cols

    // ---- weights: per tap-row i, per pixel-pair (A=px01, B=px23):
    //   W0,W2,W4 : even-tap pairs for acc01/acc23
    //   Wm       : (w1 for hi-px, w3 for lo-px) used with the middle aligned pair
    //   s1,s3    : leftover scalar taps
    u64 W0A[5], W2A[5], W4A[5], WmA[5];
    u64 W0B[5], W2B[5], W4B[5], WmB[5];
    float s1A[5], s3A[5], s1B[5], s3B[5];
    {
        const float* wp = in2 + ((size_t)n * KTAPS * HDIM + h) * WDIM + w0;
#pragma unroll
        for (int i = 0; i < 5; i++) {
            float4 v0 = __ldcs((const float4*)(wp + (size_t)(5 * i + 0) * PLANE));
            float4 v1 = __ldcs((const float4*)(wp + (size_t)(5 * i + 1) * PLANE));
            float4 v2 = __ldcs((const float4*)(wp + (size_t)(5 * i + 2) * PLANE));
            float4 v3 = __ldcs((const float4*)(wp + (size_t)(5 * i + 3) * PLANE));
            float4 v4 = __ldcs((const float4*)(wp + (size_t)(5 * i + 4) * PLANE));
            W0A[i] = pack2(v0.x, v0.y);  W0B[i] = pack2(v0.z, v0.w);
            W2A[i] = pack2(v2.x, v2.y);  W2B[i] = pack2(v2.z, v2.w);
            W4A[i] = pack2(v4.x, v4.y);  W4B[i] = pack2(v4.z, v4.w);
            WmA[i] = pack2(v1.y, v3.x);  WmB[i] = pack2(v1.w, v3.z);
            s1A[i] = v1.x;  s3A[i] = v3.y;
            s1B[i] = v1.z;  s3B[i] = v3.w;
        }
    }

    // ---- copy roles: up to 2 16B chunks per thread per channel ----
    const float* in1n = in1 + (size_t)n * CDIM * PLANE;
    int  goff0 = 0, goff1 = 0, cpsz0 = 0, cpsz1 = 0, soff0 = 0, soff1 = 0;
    bool act1 = false;
    {
        int k = tid;                                  // chunk 0 (always active)
        int r = k / CHUNKS_PER_ROW, ch = k - r * CHUNKS_PER_ROW;
        int gy = hbase - 2 + r, gx0 = wbase - 4 + 4 * ch;
        bool v = (gy >= 0) && (gy < HDIM) && (gx0 >= 0) && (gx0 + 3 < WDIM);
        goff0 = v ? (gy * WDIM + gx0) : 0;
        cpsz0 = v ? 16 : 0;
        soff0 = r * SPITCH + 4 * ch;

        k = tid + NTHR;                               // chunk 1
        act1 = (k < NCHUNK);
        r = k / CHUNKS_PER_ROW; ch = k - r * CHUNKS_PER_ROW;
        gy = hbase - 2 + r; gx0 = wbase - 4 + 4 * ch;
        v = act1 && (gy >= 0) && (gy < HDIM) && (gx0 >= 0) && (gx0 + 3 < WDIM);
        goff1 = v ? (gy * WDIM + gx0) : 0;
        cpsz1 = v ? 16 : 0;
        soff1 = r * SPITCH + 4 * ch;
    }

    float* po = out + (size_t)n * CDIM * PLANE + (size_t)h * WDIM + w0;

    auto issue = [&](int p, int s) {
        const float* srcA = in1n + (size_t)(2 * p) * PLANE;
        const float* srcB = srcA + PLANE;
        uint32_t dA = smem_u32(&ring[s][0][0]);
        uint32_t dB = smem_u32(&ring[s][1][0]);
        cp_async16(dA + 4 * soff0, srcA + goff0, cpsz0);
        cp_async16(dB + 4 * soff0, srcB + goff0, cpsz0);
        if (act1) {
            cp_async16(dA + 4 * soff1, srcA + goff1, cpsz1);
            cp_async16(dB + 4 * soff1, srcB + goff1, cpsz1);
        }
        cp_commit();
    };

    // ---- prologue: pairs 0..2 (channels 0..5) in flight ----
    issue(0, 0);
    issue(1, 1);
    issue(2, 2);

#pragma unroll 1
    for (int p = 0; p < NPAIR; p++) {
        const int s = p & (STAGES - 1);

        cp_wait2();
        __syncthreads();

        if (p + 3 < NPAIR) issue(p + 3, (p + 3) & (STAGES - 1));
        else               cp_commit();

#pragma unroll
        for (int half = 0; half < 2; half++) {
            // staged col0 = wbase-4; window d0 = col w0-2 -> 4*tx+2
            const float* basep = &ring[s][half][ty * SPITCH + 4 * tx + 2];
            u64 a01 = 0, a10 = 0, a23 = 0, a32 = 0;
            float e0 = 0.f, e1 = 0.f, e2 = 0.f, e3 = 0.f;
#pragma unroll
            for (int i = 0; i < 5; i++) {
                const float* rp = basep + i * SPITCH;
                float2 A  = *(const float2*)(rp);       // d0 d1
                float4 Bq = *(const float4*)(rp + 2);   // d2..d5
                float2 C  = *(const float2*)(rp + 6);   // d6 d7
                u64 q01 = pack2(A.x, A.y);    // aligned reg pairs: no MOVs
                u64 q23 = pack2(Bq.x, Bq.y);
                u64 q45 = pack2(Bq.z, Bq.w);
                u64 q67 = pack2(C.x, C.y);

                // pair A = (px0, px1), window d0..d5
                fma2(a01, q01, W0A[i]);      // d0*w0 | d1*w0
                fma2(a01, q23, W2A[i]);      // d2*w2 | d3*w2
                fma2(a01, q45, W4A[i]);      // d4*w4 | d5*w4
                fma2(a10, q23, WmA[i]);      // d2*w1(px1) | d3*w3(px0)
                e0 = fmaf(A.y,  s1A[i], e0); // d1*w1(px0)
                e1 = fmaf(Bq.z, s3A[i], e1); // d4*w3(px1)

                // pair B = (px2, px3), window d2..d7
                fma2(a23, q23, W0B[i]);      // d2*w0 | d3*w0
                fma2(a23, q45, W2B[i]);      // d4*w2 | d5*w2
                fma2(a23, q67, W4B[i]);      // d6*w4 | d7*w4
                fma2(a32, q45, WmB[i]);      // d4*w1(px3) | d5*w3(px2)
                e2 = fmaf(Bq.y, s1B[i], e2); // d3*w1(px2)
                e3 = fmaf(C.x,  s3B[i], e3); // d6*w3(px3)
            }
            float p0a, p1a, p1b, p0b, p2a, p3a, p3b, p2b;
            unpack2(a01, p0a, p1a);
            unpack2(a10, p1b, p0b);
            unpack2(a23, p2a, p3a);
            unpack2(a32, p3b, p2b);
            float4 o;
            o.x = p0a + p0b + e0;
            o.y = p1a + p1b + e1;
            o.z = p2a + p2b + e2;
            o.w = p3a + p3b + e3;
            __stcs((float4*)(po + (size_t)(2 * p + half) * PLANE), o);
        }
    }
}

extern "C" void kernel_launch(void* const* d_in, const int* in_sizes, int n_in,
                              void* d_out, int out_size) {
    const float* in1 = (const float*)d_in[0];
    const float* in2 = (const float*)d_in[1];
    float* out = (float*)d_out;

    dim3 block(BX, BY);
    dim3 grid(WDIM / TILE_W, HDIM / TILE_H, NDIM);  // 12 x 48 x 4
    lga_kernel<<<grid, block>>>(in1, in2, out);
}